// round 2
// baseline (speedup 1.0000x reference)
#include <cuda_runtime.h>
#include <math.h>

// Problem constants
#define SEQ   512
#define BATCH 64
#define HID   1024
#define NIN   512
#define NOUT  512
#define NCTA  128      // persistent recurrence grid: 16 j-tiles x 8 k-chunks

// Scratch (device globals: allocation-free rule)
__device__ float g_xi[(size_t)BATCH * SEQ * HID];   // [b][s][h] input projection
__device__ float g_h [(size_t)BATCH * SEQ * HID];   // [b][s][h] hidden states
__device__ float g_part[8 * BATCH * HID];           // split-K partials for one step

// Grid barrier state
__device__ unsigned g_cnt = 0;
__device__ volatile unsigned g_gen = 0;

__device__ __forceinline__ void gbar()
{
    __syncthreads();
    if (threadIdx.x == 0) {
        unsigned gen = g_gen;
        __threadfence();                        // release: my writes visible
        if (atomicAdd(&g_cnt, 1u) == NCTA - 1) {
            g_cnt = 0;
            __threadfence();
            g_gen = gen + 1;                    // publish
        } else {
            while (g_gen == gen) { __nanosleep(32); }
        }
        __threadfence();                        // acquire: others' writes visible
    }
    __syncthreads();
}

// ---------------------------------------------------------------------------
// Generic 64x64-tile SGEMM with bias: C[M,N] = A[M,K] * Bm[K,N] + bias[N]
// ---------------------------------------------------------------------------
template<int K, int N>
__global__ __launch_bounds__(256) void gemm_bias(
    const float* __restrict__ A, const float* __restrict__ Bm,
    const float* __restrict__ bias, float* __restrict__ C)
{
    __shared__ float As[16][68];   // transposed A tile: As[k][m], padded
    __shared__ float Bs[16][64];   // Bs[k][n]

    const int tid = threadIdx.x;
    const int tx = tid & 15, ty = tid >> 4;
    const int row0 = blockIdx.y * 64;
    const int col0 = blockIdx.x * 64;

    const int a_r = tid >> 2, a_k = (tid & 3) << 2;   // A: 64 rows x 16 k
    const int b_k = tid >> 4, b_c = (tid & 15) << 2;  // B: 16 k x 64 cols

    const float* Ap = A + (size_t)(row0 + a_r) * K + a_k;
    const float* Bp = Bm + (size_t)b_k * N + col0 + b_c;

    float acc[4][4] = {};

    for (int k0 = 0; k0 < K; k0 += 16) {
        float4 av = *(const float4*)(Ap + k0);
        float4 bv = *(const float4*)(Bp + (size_t)k0 * N);
        As[a_k + 0][a_r] = av.x;
        As[a_k + 1][a_r] = av.y;
        As[a_k + 2][a_r] = av.z;
        As[a_k + 3][a_r] = av.w;
        *(float4*)&Bs[b_k][b_c] = bv;
        __syncthreads();
#pragma unroll
        for (int kk = 0; kk < 16; kk++) {
            float4 a = *(const float4*)&As[kk][ty << 2];
            float4 b = *(const float4*)&Bs[kk][tx << 2];
            acc[0][0] = fmaf(a.x, b.x, acc[0][0]);
            acc[0][1] = fmaf(a.x, b.y, acc[0][1]);
            acc[0][2] = fmaf(a.x, b.z, acc[0][2]);
            acc[0][3] = fmaf(a.x, b.w, acc[0][3]);
            acc[1][0] = fmaf(a.y, b.x, acc[1][0]);
            acc[1][1] = fmaf(a.y, b.y, acc[1][1]);
            acc[1][2] = fmaf(a.y, b.z, acc[1][2]);
            acc[1][3] = fmaf(a.y, b.w, acc[1][3]);
            acc[2][0] = fmaf(a.z, b.x, acc[2][0]);
            acc[2][1] = fmaf(a.z, b.y, acc[2][1]);
            acc[2][2] = fmaf(a.z, b.z, acc[2][2]);
            acc[2][3] = fmaf(a.z, b.w, acc[2][3]);
            acc[3][0] = fmaf(a.w, b.x, acc[3][0]);
            acc[3][1] = fmaf(a.w, b.y, acc[3][1]);
            acc[3][2] = fmaf(a.w, b.z, acc[3][2]);
            acc[3][3] = fmaf(a.w, b.w, acc[3][3]);
        }
        __syncthreads();
    }

    float4 bb = *(const float4*)&bias[col0 + (tx << 2)];
#pragma unroll
    for (int i = 0; i < 4; i++) {
        float4 o = make_float4(acc[i][0] + bb.x, acc[i][1] + bb.y,
                               acc[i][2] + bb.z, acc[i][3] + bb.w);
        *(float4*)&C[(size_t)(row0 + (ty << 2) + i) * N + col0 + (tx << 2)] = o;
    }
}

// ---------------------------------------------------------------------------
// Persistent recurrence kernel: 128 CTAs, CTA = (jt = bx & 15, kc = bx >> 4).
// Wh slice [kc*128 .. +128) x [jt*64 .. +64) cached in smem for all steps.
// Per step: split-K partial GEMM -> gbar -> fused reduce+tanh+relu -> gbar.
// ---------------------------------------------------------------------------
__global__ __launch_bounds__(256) void rnn_recurrence(const float* __restrict__ Wh)
{
    __shared__ float As[16][68];    // transposed h-prev chunk: As[k][b]
    __shared__ float Bs[128][64];   // persistent Wh slice: Bs[k][j]

    const int tid = threadIdx.x;
    const int jt  = blockIdx.x & 15;
    const int kc  = blockIdx.x >> 4;
    const int col0  = jt << 6;       // j offset
    const int kbase = kc << 7;       // k offset

    const int tx = tid & 15, ty = tid >> 4;
    const int a_r = tid >> 2, a_k = (tid & 3) << 2;

    // Load persistent Wh slice: 128 k x 64 j
    for (int i = tid; i < 128 * 16; i += 256) {
        int k = i >> 4, c = (i & 15) << 2;
        *(float4*)&Bs[k][c] =
            *(const float4*)&Wh[(size_t)(kbase + k) * HID + col0 + c];
    }

    // h_0 = relu(tanh(xi_0)) : all 32768 threads, float2 each
    {
        const int g = blockIdx.x * 256 + tid;
        const size_t e0 = (size_t)g << 1;
        const int b = (int)(e0 >> 10);
        const int j = (int)(e0 & (HID - 1));
        const size_t off = (size_t)b * (SEQ * HID) + j;
        float2 v = *(const float2*)&g_xi[off];
        v.x = fmaxf(tanhf(v.x), 0.0f);
        v.y = fmaxf(tanhf(v.y), 0.0f);
        *(float2*)&g_h[off] = v;
    }
    __threadfence();
    gbar();     // also makes Bs visible CTA-wide

    for (int t = 1; t < SEQ; t++) {
        // ---- phase A: partial GEMM over this CTA's K-chunk ----
        const float* hprev = g_h + (size_t)(t - 1) * HID;   // + b*SEQ*HID
        float acc[4][4] = {};

        for (int k0 = 0; k0 < 128; k0 += 16) {
            float4 av = *(const float4*)(hprev + (size_t)a_r * (SEQ * HID)
                                         + kbase + k0 + a_k);
            As[a_k + 0][a_r] = av.x;
            As[a_k + 1][a_r] = av.y;
            As[a_k + 2][a_r] = av.z;
            As[a_k + 3][a_r] = av.w;
            __syncthreads();
#pragma unroll
            for (int kk = 0; kk < 16; kk++) {
                float4 a = *(const float4*)&As[kk][ty << 2];
                float4 b = *(const float4*)&Bs[k0 + kk][tx << 2];
                acc[0][0] = fmaf(a.x, b.x, acc[0][0]);
                acc[0][1] = fmaf(a.x, b.y, acc[0][1]);
                acc[0][2] = fmaf(a.x, b.z, acc[0][2]);
                acc[0][3] = fmaf(a.x, b.w, acc[0][3]);
                acc[1][0] = fmaf(a.y, b.x, acc[1][0]);
                acc[1][1] = fmaf(a.y, b.y, acc[1][1]);
                acc[1][2] = fmaf(a.y, b.z, acc[1][2]);
                acc[1][3] = fmaf(a.y, b.w, acc[1][3]);
                acc[2][0] = fmaf(a.z, b.x, acc[2][0]);
                acc[2][1] = fmaf(a.z, b.y, acc[2][1]);
                acc[2][2] = fmaf(a.z, b.z, acc[2][2]);
                acc[2][3] = fmaf(a.z, b.w, acc[2][3]);
                acc[3][0] = fmaf(a.w, b.x, acc[3][0]);
                acc[3][1] = fmaf(a.w, b.y, acc[3][1]);
                acc[3][2] = fmaf(a.w, b.z, acc[3][2]);
                acc[3][3] = fmaf(a.w, b.w, acc[3][3]);
            }
            __syncthreads();
        }

#pragma unroll
        for (int i = 0; i < 4; i++) {
            int b = (ty << 2) + i;
            *(float4*)&g_part[(size_t)kc * (BATCH * HID)
                              + (size_t)b * HID + col0 + (tx << 2)] =
                make_float4(acc[i][0], acc[i][1], acc[i][2], acc[i][3]);
        }
        __threadfence();
        gbar();

        // ---- phase B: reduce partials + xi_t, tanh, relu -> h_t ----
        {
            const int g = blockIdx.x * 256 + tid;
            const size_t e0 = (size_t)g << 1;
            const int b = (int)(e0 >> 10);
            const int j = (int)(e0 & (HID - 1));
            const size_t off = (size_t)b * (SEQ * HID) + (size_t)t * HID + j;
            float2 v = *(const float2*)&g_xi[off];
#pragma unroll
            for (int c = 0; c < 8; c++) {
                float2 p = *(const float2*)&g_part[(size_t)c * (BATCH * HID) + e0];
                v.x += p.x; v.y += p.y;
            }
            v.x = fmaxf(tanhf(v.x), 0.0f);
            v.y = fmaxf(tanhf(v.y), 0.0f);
            *(float2*)&g_h[off] = v;
        }
        __threadfence();
        gbar();
    }
}

// ---------------------------------------------------------------------------
extern "C" void kernel_launch(void* const* d_in, const int* in_sizes, int n_in,
                              void* d_out, int out_size)
{
    const float* x  = (const float*)d_in[0];
    const float* Wi = (const float*)d_in[1];
    const float* bi = (const float*)d_in[2];
    const float* Wh = (const float*)d_in[3];
    const float* Wo = (const float*)d_in[4];
    const float* bo = (const float*)d_in[5];
    float* out = (float*)d_out;

    void* p;
    cudaGetSymbolAddress(&p, g_xi);
    float* xi = (float*)p;
    cudaGetSymbolAddress(&p, g_h);
    float* hh = (float*)p;

    // 1) xi = x @ Wi + bi   (M = 32768, K = 512, N = 1024)
    gemm_bias<NIN, HID><<<dim3(HID / 64, (BATCH * SEQ) / 64), 256>>>(x, Wi, bi, xi);

    // 2) whole recurrence in one persistent kernel (grid barrier inside)
    rnn_recurrence<<<NCTA, 256>>>(Wh);

    // 3) y = h @ Wo + bo   (M = 32768, K = 1024, N = 512)
    gemm_bias<HID, NOUT><<<dim3(NOUT / 64, (BATCH * SEQ) / 64), 256>>>(hh, Wo, bo, out);
}

// round 5
// speedup vs baseline: 1.5476x; 1.5476x over previous
#include <cuda_runtime.h>
#include <math.h>

// Problem constants
#define SEQ   512
#define BATCH 64
#define HID   1024
#define NIN   512
#define NOUT  512
#define NCTA  128     // recurrence grid: 8 j-tiles(128) x 16 k-chunks(64)
#define NJT   8
#define NKC   16

// Scratch (device globals). Layout of xi/h: [s][b][h]
__device__ float g_xi[(size_t)SEQ * BATCH * HID];
__device__ float g_h [(size_t)SEQ * BATCH * HID];
__device__ float g_part[NKC * BATCH * HID];       // split-K partials (one step)

// Barrier state (monotonic counters within one launch; reset kernel zeroes
// them before every recurrence launch so graph replays are deterministic)
__device__ unsigned g_cnt = 0;
__device__ unsigned g_grp[NJT * 32];              // padded 128B apart

__global__ void reset_barriers()
{
    if (threadIdx.x == 0) g_cnt = 0;
    if (threadIdx.x < NJT) g_grp[threadIdx.x << 5] = 0;
}

__device__ __forceinline__ void gbar(int* bcount)
{
    __syncthreads();
    ++*bcount;
    if (threadIdx.x == 0) {
        __threadfence();
        atomicAdd(&g_cnt, 1u);
        const unsigned target = (unsigned)(NCTA * *bcount);
        while (*(volatile unsigned*)&g_cnt < target) {}
        __threadfence();
    }
    __syncthreads();
}

// ---------------------------------------------------------------------------
// 128x128x8 SGEMM with bias + output-row permutation.
// PERM=1: A rows m=(b*512+s) -> C row (s*64+b)   [GEMM1: x->xi]
// PERM=2: A rows m=(s*64+b)  -> C row (b*512+s)  [GEMM3: h->y]
// 256 threads, 8x8 micro-tile in 4x4 quadrants, register-prefetch pipeline.
// ---------------------------------------------------------------------------
template<int K, int N, int PERM>
__global__ __launch_bounds__(256, 2) void gemm128(
    const float* __restrict__ A, const float* __restrict__ Bm,
    const float* __restrict__ bias, float* __restrict__ C)
{
    __shared__ float As[8][132];   // k x m, padded (132*4B = 16B-aligned rows)
    __shared__ float Bs[8][128];

    const int tid = threadIdx.x;
    const int tx = tid & 15, ty = tid >> 4;
    const int row0 = blockIdx.y * 128, col0 = blockIdx.x * 128;

    const int a_r = tid >> 1, a_k = (tid & 1) << 2;   // 128 rows x 8 k
    const int b_k = tid >> 5, b_c = (tid & 31) << 2;  // 8 k x 128 cols

    const float* Ap = A + (size_t)(row0 + a_r) * K + a_k;
    const float* Bp = Bm + (size_t)b_k * N + col0 + b_c;

    float4 ar = *(const float4*)Ap;
    float4 br = *(const float4*)Bp;

    float acc[8][8] = {};

    for (int k0 = 0; k0 < K; k0 += 8) {
        As[a_k + 0][a_r] = ar.x;
        As[a_k + 1][a_r] = ar.y;
        As[a_k + 2][a_r] = ar.z;
        As[a_k + 3][a_r] = ar.w;
        *(float4*)&Bs[b_k][b_c] = br;
        __syncthreads();
        if (k0 + 8 < K) {
            ar = *(const float4*)(Ap + k0 + 8);
            br = *(const float4*)(Bp + (size_t)(k0 + 8) * N);
        }
#pragma unroll
        for (int kk = 0; kk < 8; kk++) {
            float4 a0 = *(const float4*)&As[kk][ty << 2];
            float4 a1 = *(const float4*)&As[kk][(ty << 2) + 64];
            float4 b0 = *(const float4*)&Bs[kk][tx << 2];
            float4 b1 = *(const float4*)&Bs[kk][(tx << 2) + 64];
            float av[8] = {a0.x, a0.y, a0.z, a0.w, a1.x, a1.y, a1.z, a1.w};
            float bv[8] = {b0.x, b0.y, b0.z, b0.w, b1.x, b1.y, b1.z, b1.w};
#pragma unroll
            for (int i = 0; i < 8; i++)
#pragma unroll
                for (int j = 0; j < 8; j++)
                    acc[i][j] = fmaf(av[i], bv[j], acc[i][j]);
        }
        __syncthreads();
    }

    float4 bb0 = *(const float4*)&bias[col0 + (tx << 2)];
    float4 bb1 = *(const float4*)&bias[col0 + (tx << 2) + 64];
#pragma unroll
    for (int i = 0; i < 8; i++) {
        const int mloc = (i < 4) ? ((ty << 2) + i) : ((ty << 2) + i + 60);
        const int m = row0 + mloc;
        size_t r;
        if (PERM == 1)      r = (size_t)((m & 511) * 64 + (m >> 9));
        else if (PERM == 2) r = (size_t)((m & 63) * 512 + (m >> 6));
        else                r = (size_t)m;
        float* Cr = C + r * N + col0;
        float4 o0 = make_float4(acc[i][0] + bb0.x, acc[i][1] + bb0.y,
                                acc[i][2] + bb0.z, acc[i][3] + bb0.w);
        float4 o1 = make_float4(acc[i][4] + bb1.x, acc[i][5] + bb1.y,
                                acc[i][6] + bb1.z, acc[i][7] + bb1.w);
        *(float4*)(Cr + (tx << 2)) = o0;
        *(float4*)(Cr + (tx << 2) + 64) = o1;
    }
}

// ---------------------------------------------------------------------------
// Persistent recurrence. CTA = (jt = bx&7 -> 128 cols, kc = bx>>3 -> 64 k's).
// Wh slice (64k x 128j, 32KB) persistent in smem. Per step:
//   partial GEMM (64b x 128j over k-chunk) -> group arrive ->
//   group wait (16 CTAs) -> each CTA reduces its 4-row slice (+tanh,relu) ->
//   one global barrier.
// ---------------------------------------------------------------------------
__global__ __launch_bounds__(256) void rnn_recurrence(const float* __restrict__ Wh)
{
    __shared__ float As[16][68];    // k x b staging; 68*4B rows = 16B-aligned
    __shared__ float Bs[64][128];   // persistent Wh slice [k][j]

    const int tid = threadIdx.x;
    const int jt = blockIdx.x & 7;
    const int kc = blockIdx.x >> 3;
    const int col0 = jt << 7;
    const int kbase = kc << 6;
    const int tx = tid & 15, ty = tid >> 4;
    const int a_r = tid >> 2, a_k = (tid & 3) << 2;

    // Load persistent Wh slice (coalesced)
#pragma unroll
    for (int i = 0; i < 8; i++) {
        int e = (i * 256 + tid) << 2;
        int k = e >> 7, c = e & 127;
        *(float4*)&Bs[k][c] = *(const float4*)&Wh[(size_t)(kbase + k) * HID + col0 + c];
    }

    int bcount = 0;

    // h_0 = relu(tanh(xi_0)) ; each CTA does 512 contiguous elems
    {
        const size_t e = ((size_t)blockIdx.x << 9) + (tid << 1);
        float2 v = *(const float2*)&g_xi[e];
        v.x = fmaxf(tanhf(v.x), 0.0f);
        v.y = fmaxf(tanhf(v.y), 0.0f);
        *(float2*)&g_h[e] = v;
    }
    __threadfence();
    gbar(&bcount);

    for (int t = 1; t < SEQ; t++) {
        // ---- phase A: partial GEMM over this CTA's 64-wide K chunk ----
        const float* hprev = g_h + (size_t)(t - 1) * (BATCH * HID);
        float acc[4][8] = {};

        float4 av = *(const float4*)&hprev[(size_t)a_r * HID + kbase + a_k];
        for (int k0 = 0; k0 < 64; k0 += 16) {
            As[a_k + 0][a_r] = av.x;
            As[a_k + 1][a_r] = av.y;
            As[a_k + 2][a_r] = av.z;
            As[a_k + 3][a_r] = av.w;
            __syncthreads();
            if (k0 + 16 < 64)
                av = *(const float4*)&hprev[(size_t)a_r * HID + kbase + k0 + 16 + a_k];
#pragma unroll
            for (int kk = 0; kk < 16; kk++) {
                float4 a = *(const float4*)&As[kk][ty << 2];
                float4 b0 = *(const float4*)&Bs[k0 + kk][tx << 2];
                float4 b1 = *(const float4*)&Bs[k0 + kk][(tx << 2) + 64];
                float avf[4] = {a.x, a.y, a.z, a.w};
                float bvf[8] = {b0.x, b0.y, b0.z, b0.w, b1.x, b1.y, b1.z, b1.w};
#pragma unroll
                for (int i = 0; i < 4; i++)
#pragma unroll
                    for (int j = 0; j < 8; j++)
                        acc[i][j] = fmaf(avf[i], bvf[j], acc[i][j]);
            }
            __syncthreads();
        }

#pragma unroll
        for (int i = 0; i < 4; i++) {
            const int b = (ty << 2) + i;
            float* pp = &g_part[(size_t)kc * (BATCH * HID) + (size_t)b * HID + col0];
            *(float4*)(pp + (tx << 2)) =
                make_float4(acc[i][0], acc[i][1], acc[i][2], acc[i][3]);
            *(float4*)(pp + (tx << 2) + 64) =
                make_float4(acc[i][4], acc[i][5], acc[i][6], acc[i][7]);
        }
        __threadfence();
        __syncthreads();

        // ---- group arrive + wait (16 CTAs sharing this jt) ----
        if (tid == 0) {
            atomicAdd(&g_grp[jt << 5], 1u);
            const unsigned target = (unsigned)(NKC * t);
            while (*(volatile unsigned*)&g_grp[jt << 5] < target) {}
            __threadfence();
        }
        __syncthreads();

        // ---- phase B: reduce own 4-row slice, tanh, relu -> h_t ----
        {
            const int b = (kc << 2) + (tid >> 6);
            const int c = col0 + ((tid & 63) << 1);
            const size_t eo = (size_t)b * HID + c;
            const size_t off = (size_t)t * (BATCH * HID) + eo;
            float2 v = *(const float2*)&g_xi[off];
#pragma unroll
            for (int q = 0; q < NKC; q++) {
                float2 p = *(const float2*)&g_part[(size_t)q * (BATCH * HID) + eo];
                v.x += p.x;
                v.y += p.y;
            }
            v.x = fmaxf(tanhf(v.x), 0.0f);
            v.y = fmaxf(tanhf(v.y), 0.0f);
            *(float2*)&g_h[off] = v;
        }
        __threadfence();
        gbar(&bcount);
    }
}

// ---------------------------------------------------------------------------
extern "C" void kernel_launch(void* const* d_in, const int* in_sizes, int n_in,
                              void* d_out, int out_size)
{
    const float* x  = (const float*)d_in[0];
    const float* Wi = (const float*)d_in[1];
    const float* bi = (const float*)d_in[2];
    const float* Wh = (const float*)d_in[3];
    const float* Wo = (const float*)d_in[4];
    const float* bo = (const float*)d_in[5];
    float* out = (float*)d_out;

    void* p;
    cudaGetSymbolAddress(&p, g_xi);
    float* xi = (float*)p;
    cudaGetSymbolAddress(&p, g_h);
    float* hh = (float*)p;

    // 0) zero barrier counters so every graph replay starts clean
    reset_barriers<<<1, 32>>>();

    // 1) xi[s][b][h] = x @ Wi + bi   (M=32768, K=512, N=1024, PERM bs->sb)
    gemm128<NIN, HID, 1><<<dim3(HID / 128, (BATCH * SEQ) / 128), 256>>>(x, Wi, bi, xi);

    // 2) whole recurrence in one persistent kernel
    rnn_recurrence<<<NCTA, 256>>>(Wh);

    // 3) y[b][s][o] = h @ Wo + bo    (M=32768, K=1024, N=512, PERM sb->bs)
    gemm128<HID, NOUT, 2><<<dim3(NOUT / 128, (BATCH * SEQ) / 128), 256>>>(hh, Wo, bo, out);
}

// round 6
// speedup vs baseline: 1.5627x; 1.0097x over previous
#include <cuda_runtime.h>
#include <math.h>

// Problem constants
#define SEQ   512
#define BATCH 64
#define HID   1024
#define NIN   512
#define NOUT  512
#define NCTA  128     // recurrence grid: 8 j-tiles(128) x 16 k-chunks(64)
#define NJT   8
#define NKC   16

// Scratch (device globals). Layout of xi/h: [s][b][h]
__device__ float g_xi[(size_t)SEQ * BATCH * HID];
__device__ float g_h [(size_t)SEQ * BATCH * HID];
__device__ float g_part[2][NKC * BATCH * HID];    // parity double-buffered partials

// Dataflow counters (monotonic within a launch; reset node before each replay)
// grp[jt]  : # phase-A completions in group jt (16 per step)
// done[jt] : # phase-B (h-slice written) completions in group jt (16 per step)
__device__ unsigned g_grp [NJT * 32];             // padded 128B apart
__device__ unsigned g_done[NJT * 32];

__global__ void reset_barriers()
{
    if (threadIdx.x < NJT) {
        g_grp [threadIdx.x << 5] = 0;
        g_done[threadIdx.x << 5] = 0;
    }
}

// ---------------------------------------------------------------------------
// 128x128x8 SGEMM with bias + output-row permutation.
// PERM=1: A rows m=(b*512+s) -> C row (s*64+b)   [GEMM1: x->xi]
// PERM=2: A rows m=(s*64+b)  -> C row (b*512+s)  [GEMM3: h->y]
// ---------------------------------------------------------------------------
template<int K, int N, int PERM>
__global__ __launch_bounds__(256, 2) void gemm128(
    const float* __restrict__ A, const float* __restrict__ Bm,
    const float* __restrict__ bias, float* __restrict__ C)
{
    __shared__ float As[8][132];   // k x m, padded (132*4B = 16B-aligned rows)
    __shared__ float Bs[8][128];

    const int tid = threadIdx.x;
    const int tx = tid & 15, ty = tid >> 4;
    const int row0 = blockIdx.y * 128, col0 = blockIdx.x * 128;

    const int a_r = tid >> 1, a_k = (tid & 1) << 2;   // 128 rows x 8 k
    const int b_k = tid >> 5, b_c = (tid & 31) << 2;  // 8 k x 128 cols

    const float* Ap = A + (size_t)(row0 + a_r) * K + a_k;
    const float* Bp = Bm + (size_t)b_k * N + col0 + b_c;

    float4 ar = *(const float4*)Ap;
    float4 br = *(const float4*)Bp;

    float acc[8][8] = {};

    for (int k0 = 0; k0 < K; k0 += 8) {
        As[a_k + 0][a_r] = ar.x;
        As[a_k + 1][a_r] = ar.y;
        As[a_k + 2][a_r] = ar.z;
        As[a_k + 3][a_r] = ar.w;
        *(float4*)&Bs[b_k][b_c] = br;
        __syncthreads();
        if (k0 + 8 < K) {
            ar = *(const float4*)(Ap + k0 + 8);
            br = *(const float4*)(Bp + (size_t)(k0 + 8) * N);
        }
#pragma unroll
        for (int kk = 0; kk < 8; kk++) {
            float4 a0 = *(const float4*)&As[kk][ty << 2];
            float4 a1 = *(const float4*)&As[kk][(ty << 2) + 64];
            float4 b0 = *(const float4*)&Bs[kk][tx << 2];
            float4 b1 = *(const float4*)&Bs[kk][(tx << 2) + 64];
            float av[8] = {a0.x, a0.y, a0.z, a0.w, a1.x, a1.y, a1.z, a1.w};
            float bv[8] = {b0.x, b0.y, b0.z, b0.w, b1.x, b1.y, b1.z, b1.w};
#pragma unroll
            for (int i = 0; i < 8; i++)
#pragma unroll
                for (int j = 0; j < 8; j++)
                    acc[i][j] = fmaf(av[i], bv[j], acc[i][j]);
        }
        __syncthreads();
    }

    float4 bb0 = *(const float4*)&bias[col0 + (tx << 2)];
    float4 bb1 = *(const float4*)&bias[col0 + (tx << 2) + 64];
#pragma unroll
    for (int i = 0; i < 8; i++) {
        const int mloc = (i < 4) ? ((ty << 2) + i) : ((ty << 2) + i + 60);
        const int m = row0 + mloc;
        size_t r;
        if (PERM == 1)      r = (size_t)((m & 511) * 64 + (m >> 9));
        else if (PERM == 2) r = (size_t)((m & 63) * 512 + (m >> 6));
        else                r = (size_t)m;
        float* Cr = C + r * N + col0;
        float4 o0 = make_float4(acc[i][0] + bb0.x, acc[i][1] + bb0.y,
                                acc[i][2] + bb0.z, acc[i][3] + bb0.w);
        float4 o1 = make_float4(acc[i][4] + bb1.x, acc[i][5] + bb1.y,
                                acc[i][6] + bb1.z, acc[i][7] + bb1.w);
        *(float4*)(Cr + (tx << 2)) = o0;
        *(float4*)(Cr + (tx << 2) + 64) = o1;
    }
}

// ---------------------------------------------------------------------------
// Persistent recurrence with point-to-point dataflow sync (no global barrier).
// CTA = (jt = bx&7 -> 128 cols, kc = bx>>3 -> 64 k's).
// Per step t: A-wait done[kc>>1]>=16t -> partial GEMM (parity buffer t&1) ->
//             grp[jt]++ -> B-wait grp[jt]>=16t -> reduce own 4-row slice
//             (+tanh,relu) -> done[jt]++.
// ---------------------------------------------------------------------------
__global__ __launch_bounds__(256) void rnn_recurrence(const float* __restrict__ Wh)
{
    __shared__ float As[16][68];    // k x b staging; 68*4B rows = 16B-aligned
    __shared__ float Bs[64][128];   // persistent Wh slice [k][j]

    const int tid = threadIdx.x;
    const int jt = blockIdx.x & 7;
    const int kc = blockIdx.x >> 3;
    const int col0 = jt << 7;
    const int kbase = kc << 6;
    const int tx = tid & 15, ty = tid >> 4;
    const int a_r = tid >> 2, a_k = (tid & 3) << 2;
    const int src = (kc >> 1) << 5;   // padded index of producer group counter
    const int own = jt << 5;

    // Load persistent Wh slice (coalesced)
#pragma unroll
    for (int i = 0; i < 8; i++) {
        int e = (i * 256 + tid) << 2;
        int k = e >> 7, c = e & 127;
        *(float4*)&Bs[k][c] = *(const float4*)&Wh[(size_t)(kbase + k) * HID + col0 + c];
    }

    // h_0 init on exactly this CTA's phase-B slice: rows [4kc..4kc+4),
    // cols [128jt..+128). Then done[jt]++ (so done[g] reaches 16 per group).
    {
        const int b = (kc << 2) + (tid >> 6);
        const int c = col0 + ((tid & 63) << 1);
        const size_t off = (size_t)b * HID + c;
        float2 v = *(const float2*)&g_xi[off];
        v.x = fmaxf(tanhf(v.x), 0.0f);
        v.y = fmaxf(tanhf(v.y), 0.0f);
        *(float2*)&g_h[off] = v;
    }
    __threadfence();
    __syncthreads();
    if (tid == 0) atomicAdd(&g_done[own], 1u);

    for (int t = 1; t < SEQ; t++) {
        // ---- A-wait: h(t-1) cols [64kc..+64) ready (producer group kc>>1) ----
        if (tid == 0) {
            const unsigned target = (unsigned)(NKC * t);
            while (*(volatile unsigned*)&g_done[src] < target) {}
            __threadfence();
        }
        __syncthreads();

        // ---- phase A: partial GEMM over this CTA's 64-wide K chunk ----
        const float* hprev = g_h + (size_t)(t - 1) * (BATCH * HID);
        float* part = g_part[t & 1];
        float acc[4][8] = {};

        float4 av = *(const float4*)&hprev[(size_t)a_r * HID + kbase + a_k];
        for (int k0 = 0; k0 < 64; k0 += 16) {
            As[a_k + 0][a_r] = av.x;
            As[a_k + 1][a_r] = av.y;
            As[a_k + 2][a_r] = av.z;
            As[a_k + 3][a_r] = av.w;
            __syncthreads();
            if (k0 + 16 < 64)
                av = *(const float4*)&hprev[(size_t)a_r * HID + kbase + k0 + 16 + a_k];
#pragma unroll
            for (int kk = 0; kk < 16; kk++) {
                float4 a = *(const float4*)&As[kk][ty << 2];
                float4 b0 = *(const float4*)&Bs[k0 + kk][tx << 2];
                float4 b1 = *(const float4*)&Bs[k0 + kk][(tx << 2) + 64];
                float avf[4] = {a.x, a.y, a.z, a.w};
                float bvf[8] = {b0.x, b0.y, b0.z, b0.w, b1.x, b1.y, b1.z, b1.w};
#pragma unroll
                for (int i = 0; i < 4; i++)
#pragma unroll
                    for (int j = 0; j < 8; j++)
                        acc[i][j] = fmaf(avf[i], bvf[j], acc[i][j]);
            }
            __syncthreads();
        }

#pragma unroll
        for (int i = 0; i < 4; i++) {
            const int b = (ty << 2) + i;
            float* pp = &part[(size_t)kc * (BATCH * HID) + (size_t)b * HID + col0];
            *(float4*)(pp + (tx << 2)) =
                make_float4(acc[i][0], acc[i][1], acc[i][2], acc[i][3]);
            *(float4*)(pp + (tx << 2) + 64) =
                make_float4(acc[i][4], acc[i][5], acc[i][6], acc[i][7]);
        }
        __threadfence();
        __syncthreads();

        // ---- group arrive + wait (16 CTAs sharing this jt) ----
        if (tid == 0) {
            atomicAdd(&g_grp[own], 1u);
            const unsigned target = (unsigned)(NKC * t);
            while (*(volatile unsigned*)&g_grp[own] < target) {}
            __threadfence();
        }
        __syncthreads();

        // ---- phase B: reduce own 4-row slice, tanh, relu -> h_t ----
        {
            const int b = (kc << 2) + (tid >> 6);
            const int c = col0 + ((tid & 63) << 1);
            const size_t eo = (size_t)b * HID + c;
            const size_t off = (size_t)t * (BATCH * HID) + eo;
            float2 v = *(const float2*)&g_xi[off];
#pragma unroll
            for (int q = 0; q < NKC; q++) {
                float2 p = *(const float2*)&part[(size_t)q * (BATCH * HID) + eo];
                v.x += p.x;
                v.y += p.y;
            }
            v.x = fmaxf(tanhf(v.x), 0.0f);
            v.y = fmaxf(tanhf(v.y), 0.0f);
            *(float2*)&g_h[off] = v;
        }
        __threadfence();
        __syncthreads();
        if (tid == 0) atomicAdd(&g_done[own], 1u);
    }
}

// ---------------------------------------------------------------------------
extern "C" void kernel_launch(void* const* d_in, const int* in_sizes, int n_in,
                              void* d_out, int out_size)
{
    const float* x  = (const float*)d_in[0];
    const float* Wi = (const float*)d_in[1];
    const float* bi = (const float*)d_in[2];
    const float* Wh = (const float*)d_in[3];
    const float* Wo = (const float*)d_in[4];
    const float* bo = (const float*)d_in[5];
    float* out = (float*)d_out;

    void* p;
    cudaGetSymbolAddress(&p, g_xi);
    float* xi = (float*)p;
    cudaGetSymbolAddress(&p, g_h);
    float* hh = (float*)p;

    // 0) zero dataflow counters so every graph replay starts clean
    reset_barriers<<<1, 32>>>();

    // 1) xi[s][b][h] = x @ Wi + bi   (M=32768, K=512, N=1024, PERM bs->sb)
    gemm128<NIN, HID, 1><<<dim3(HID / 128, (BATCH * SEQ) / 128), 256>>>(x, Wi, bi, xi);

    // 2) whole recurrence in one persistent kernel (dataflow sync inside)
    rnn_recurrence<<<NCTA, 256>>>(Wh);

    // 3) y[b][s][o] = h @ Wo + bo    (M=32768, K=1024, N=512, PERM sb->bs)
    gemm128<HID, NOUT, 2><<<dim3(NOUT / 128, (BATCH * SEQ) / 128), 256>>>(hh, Wo, bo, out);
}

// round 7
// speedup vs baseline: 1.5770x; 1.0092x over previous
#include <cuda_runtime.h>
#include <math.h>

// Problem constants
#define SEQ   512
#define BATCH 64
#define HID   1024
#define NIN   512
#define NOUT  512
#define NCTA  128     // recurrence grid: 8 j-tiles(128) x 16 k-chunks(64)
#define NJT   8
#define NKC   16
#define BH    (BATCH * HID)

// Scratch (device globals). Layout of xi/h: [s][b][h]
__device__ float g_xi[(size_t)SEQ * BATCH * HID];
__device__ float g_h [(size_t)SEQ * BATCH * HID];
__device__ float g_part[2][NKC * BATCH * HID];    // parity double-buffered partials

// Dataflow counters (monotonic within a launch; reset node before each replay)
__device__ unsigned g_grp [NJT * 32];             // phase-A completions per group
__device__ unsigned g_done[NJT * 32];             // phase-B completions per group

__global__ void reset_barriers()
{
    if (threadIdx.x < NJT) {
        g_grp [threadIdx.x << 5] = 0;
        g_done[threadIdx.x << 5] = 0;
    }
}

__device__ __forceinline__ unsigned ld_acq(const unsigned* p)
{
    unsigned v;
    asm volatile("ld.acquire.gpu.global.u32 %0, [%1];" : "=r"(v) : "l"(p));
    return v;
}
__device__ __forceinline__ void arrive(unsigned* p)
{
    asm volatile("red.release.gpu.global.add.u32 [%0], 1;" :: "l"(p) : "memory");
}

// ---------------------------------------------------------------------------
// 128x128x8 SGEMM with bias + output-row permutation (unchanged, ~fp32 roofline)
// PERM=1: A rows m=(b*512+s) -> C row (s*64+b)   [GEMM1: x->xi]
// PERM=2: A rows m=(s*64+b)  -> C row (b*512+s)  [GEMM3: h->y]
// ---------------------------------------------------------------------------
template<int K, int N, int PERM>
__global__ __launch_bounds__(256, 2) void gemm128(
    const float* __restrict__ A, const float* __restrict__ Bm,
    const float* __restrict__ bias, float* __restrict__ C)
{
    __shared__ float As[8][132];
    __shared__ float Bs[8][128];

    const int tid = threadIdx.x;
    const int tx = tid & 15, ty = tid >> 4;
    const int row0 = blockIdx.y * 128, col0 = blockIdx.x * 128;

    const int a_r = tid >> 1, a_k = (tid & 1) << 2;
    const int b_k = tid >> 5, b_c = (tid & 31) << 2;

    const float* Ap = A + (size_t)(row0 + a_r) * K + a_k;
    const float* Bp = Bm + (size_t)b_k * N + col0 + b_c;

    float4 ar = *(const float4*)Ap;
    float4 br = *(const float4*)Bp;

    float acc[8][8] = {};

    for (int k0 = 0; k0 < K; k0 += 8) {
        As[a_k + 0][a_r] = ar.x;
        As[a_k + 1][a_r] = ar.y;
        As[a_k + 2][a_r] = ar.z;
        As[a_k + 3][a_r] = ar.w;
        *(float4*)&Bs[b_k][b_c] = br;
        __syncthreads();
        if (k0 + 8 < K) {
            ar = *(const float4*)(Ap + k0 + 8);
            br = *(const float4*)(Bp + (size_t)(k0 + 8) * N);
        }
#pragma unroll
        for (int kk = 0; kk < 8; kk++) {
            float4 a0 = *(const float4*)&As[kk][ty << 2];
            float4 a1 = *(const float4*)&As[kk][(ty << 2) + 64];
            float4 b0 = *(const float4*)&Bs[kk][tx << 2];
            float4 b1 = *(const float4*)&Bs[kk][(tx << 2) + 64];
            float av[8] = {a0.x, a0.y, a0.z, a0.w, a1.x, a1.y, a1.z, a1.w};
            float bv[8] = {b0.x, b0.y, b0.z, b0.w, b1.x, b1.y, b1.z, b1.w};
#pragma unroll
            for (int i = 0; i < 8; i++)
#pragma unroll
                for (int j = 0; j < 8; j++)
                    acc[i][j] = fmaf(av[i], bv[j], acc[i][j]);
        }
        __syncthreads();
    }

    float4 bb0 = *(const float4*)&bias[col0 + (tx << 2)];
    float4 bb1 = *(const float4*)&bias[col0 + (tx << 2) + 64];
#pragma unroll
    for (int i = 0; i < 8; i++) {
        const int mloc = (i < 4) ? ((ty << 2) + i) : ((ty << 2) + i + 60);
        const int m = row0 + mloc;
        size_t r;
        if (PERM == 1)      r = (size_t)((m & 511) * 64 + (m >> 9));
        else if (PERM == 2) r = (size_t)((m & 63) * 512 + (m >> 6));
        else                r = (size_t)m;
        float* Cr = C + r * N + col0;
        float4 o0 = make_float4(acc[i][0] + bb0.x, acc[i][1] + bb0.y,
                                acc[i][2] + bb0.z, acc[i][3] + bb0.w);
        float4 o1 = make_float4(acc[i][4] + bb1.x, acc[i][5] + bb1.y,
                                acc[i][6] + bb1.z, acc[i][7] + bb1.w);
        *(float4*)(Cr + (tx << 2)) = o0;
        *(float4*)(Cr + (tx << 2) + 64) = o1;
    }
}

// ---------------------------------------------------------------------------
// Persistent recurrence, 128 threads/CTA, 8x8 micro-tile (1.0 B/FMA).
// CTA = (jt = bx&7 -> 128 cols, kc = bx>>3 -> 64 k's).
// Sync: scoped release/acquire atomics, no __threadfence.
// ---------------------------------------------------------------------------
__global__ __launch_bounds__(128) void rnn_recurrence(const float* __restrict__ Wh)
{
    __shared__ float As[16][68];    // k x b staging; 68*4B rows = 16B-aligned
    __shared__ float Bs[64][128];   // persistent Wh slice [k][j]

    const int tid = threadIdx.x;
    const int jt = blockIdx.x & 7;
    const int kc = blockIdx.x >> 3;
    const int col0 = jt << 7;
    const int kbase = kc << 6;
    const int tx = tid & 15, ty = tid >> 4;     // ty 0..7
    const int a_r = tid >> 1, a_k8 = (tid & 1) << 3;
    const int src = (kc >> 1) << 5;
    const int own = jt << 5;

    // Load persistent Wh slice: 8192 floats, 16 float4 per thread
#pragma unroll
    for (int i = 0; i < 16; i++) {
        int e4 = i * 128 + tid;             // float4 index, 32 per row
        int k = e4 >> 5, c = (e4 & 31) << 2;
        *(float4*)&Bs[k][c] = *(const float4*)&Wh[(size_t)(kbase + k) * HID + col0 + c];
    }

    // h_0 init on this CTA's phase-B slice: rows [4kc..+4), cols [128jt..+128)
    {
        const int b = (kc << 2) + (tid >> 5);
        const int c = col0 + ((tid & 31) << 2);
        const size_t off = (size_t)b * HID + c;
        float4 v = *(const float4*)&g_xi[off];
        v.x = fmaxf(tanhf(v.x), 0.0f);
        v.y = fmaxf(tanhf(v.y), 0.0f);
        v.z = fmaxf(tanhf(v.z), 0.0f);
        v.w = fmaxf(tanhf(v.w), 0.0f);
        *(float4*)&g_h[off] = v;
    }
    __syncthreads();
    if (tid == 0) arrive(&g_done[own]);

    for (int t = 1; t < SEQ; t++) {
        // ---- A-wait: h(t-1) cols [64kc..+64) ready (producer group kc>>1) ----
        if (tid == 0) {
            const unsigned target = (unsigned)(NKC * t);
            while (ld_acq(&g_done[src]) < target) {}
        }
        __syncthreads();

        // ---- phase A: 64x128 partial GEMM over 64-wide K chunk, 8x8 micro ----
        const float* hprev = g_h + (size_t)(t - 1) * BH;
        float* part = g_part[t & 1];
        float acc[8][8] = {};

        const float* hrow = hprev + (size_t)a_r * HID + kbase + a_k8;
        float4 pa0 = *(const float4*)hrow;
        float4 pa1 = *(const float4*)(hrow + 4);

        for (int k0 = 0; k0 < 64; k0 += 16) {
            As[a_k8 + 0][a_r] = pa0.x;
            As[a_k8 + 1][a_r] = pa0.y;
            As[a_k8 + 2][a_r] = pa0.z;
            As[a_k8 + 3][a_r] = pa0.w;
            As[a_k8 + 4][a_r] = pa1.x;
            As[a_k8 + 5][a_r] = pa1.y;
            As[a_k8 + 6][a_r] = pa1.z;
            As[a_k8 + 7][a_r] = pa1.w;
            __syncthreads();
            if (k0 + 16 < 64) {
                pa0 = *(const float4*)(hrow + k0 + 16);
                pa1 = *(const float4*)(hrow + k0 + 20);
            }
#pragma unroll
            for (int kk = 0; kk < 16; kk++) {
                float4 a0 = *(const float4*)&As[kk][ty << 3];
                float4 a1 = *(const float4*)&As[kk][(ty << 3) + 4];
                float4 b0 = *(const float4*)&Bs[k0 + kk][tx << 3];
                float4 b1 = *(const float4*)&Bs[k0 + kk][(tx << 3) + 4];
                float av[8] = {a0.x, a0.y, a0.z, a0.w, a1.x, a1.y, a1.z, a1.w};
                float bv[8] = {b0.x, b0.y, b0.z, b0.w, b1.x, b1.y, b1.z, b1.w};
#pragma unroll
                for (int i = 0; i < 8; i++)
#pragma unroll
                    for (int j = 0; j < 8; j++)
                        acc[i][j] = fmaf(av[i], bv[j], acc[i][j]);
            }
            __syncthreads();
        }

        // Store partials: 8 rows x 8 cols per thread
#pragma unroll
        for (int i = 0; i < 8; i++) {
            const int b = (ty << 3) + i;
            float* pp = &part[(size_t)kc * BH + (size_t)b * HID + col0 + (tx << 3)];
            *(float4*)pp =
                make_float4(acc[i][0], acc[i][1], acc[i][2], acc[i][3]);
            *(float4*)(pp + 4) =
                make_float4(acc[i][4], acc[i][5], acc[i][6], acc[i][7]);
        }
        __syncthreads();

        // ---- group arrive + wait (16 CTAs sharing this jt) ----
        if (tid == 0) {
            arrive(&g_grp[own]);
            const unsigned target = (unsigned)(NKC * t);
            while (ld_acq(&g_grp[own]) < target) {}
        }
        __syncthreads();

        // ---- phase B: reduce own 4-row slice, tanh, relu -> h_t ----
        {
            const int b = (kc << 2) + (tid >> 5);
            const int c = col0 + ((tid & 31) << 2);
            const size_t eo = (size_t)b * HID + c;
            const size_t off = (size_t)t * BH + eo;
            float4 v = *(const float4*)&g_xi[off];
#pragma unroll
            for (int q = 0; q < NKC; q++) {
                float4 p = *(const float4*)&part[(size_t)q * BH + eo];
                v.x += p.x; v.y += p.y; v.z += p.z; v.w += p.w;
            }
            v.x = fmaxf(tanhf(v.x), 0.0f);
            v.y = fmaxf(tanhf(v.y), 0.0f);
            v.z = fmaxf(tanhf(v.z), 0.0f);
            v.w = fmaxf(tanhf(v.w), 0.0f);
            *(float4*)&g_h[off] = v;
        }
        __syncthreads();
        if (tid == 0) arrive(&g_done[own]);
    }
}

// ---------------------------------------------------------------------------
extern "C" void kernel_launch(void* const* d_in, const int* in_sizes, int n_in,
                              void* d_out, int out_size)
{
    const float* x  = (const float*)d_in[0];
    const float* Wi = (const float*)d_in[1];
    const float* bi = (const float*)d_in[2];
    const float* Wh = (const float*)d_in[3];
    const float* Wo = (const float*)d_in[4];
    const float* bo = (const float*)d_in[5];
    float* out = (float*)d_out;

    void* p;
    cudaGetSymbolAddress(&p, g_xi);
    float* xi = (float*)p;
    cudaGetSymbolAddress(&p, g_h);
    float* hh = (float*)p;

    // 0) zero dataflow counters so every graph replay starts clean
    reset_barriers<<<1, 32>>>();

    // 1) xi[s][b][h] = x @ Wi + bi   (M=32768, K=512, N=1024, PERM bs->sb)
    gemm128<NIN, HID, 1><<<dim3(HID / 128, (BATCH * SEQ) / 128), 256>>>(x, Wi, bi, xi);

    // 2) whole recurrence in one persistent kernel (dataflow sync inside)
    rnn_recurrence<<<NCTA, 128>>>(Wh);

    // 3) y[b][s][o] = h @ Wo + bo    (M=32768, K=1024, N=512, PERM sb->bs)
    gemm128<HID, NOUT, 2><<<dim3(NOUT / 128, (BATCH * SEQ) / 128), 256>>>(hh, Wo, bo, out);
}